// round 7
// baseline (speedup 1.0000x reference)
#include <cuda_runtime.h>

// Fixed-shape problem: logits [8,19,512,512] f32, target [8,512,512] (int32 on device)
#define NCLS 19
#define HW   262144           // 512*512
#define HW2  131072           // HW/2 (float2 pixel-pairs per image-class plane)
#define CHW  (NCLS * HW)
#define NBLK 444              // 3 CTAs per SM
#define NTHR 256

// Per-block partials: [0..18]=prob_sums, [19..37]=intersection, [38..56]=counts,
// [57]=sum w_t (x2), [58]=sum w_t*log_pt (x2), [59]=sum alpha*(1-pt)^2*log_pt (x2)
__device__ float    g_part[NBLK][64];
__device__ unsigned g_sem;     // zero-initialized; self-resetting

__device__ __forceinline__ float ex2f(float x){ float r; asm("ex2.approx.ftz.f32 %0,%1;":"=f"(r):"f"(x)); return r; }
__device__ __forceinline__ float lg2f(float x){ float r; asm("lg2.approx.ftz.f32 %0,%1;":"=f"(r):"f"(x)); return r; }
__device__ __forceinline__ float rcpf(float x){ float r; asm("rcp.approx.ftz.f32 %0,%1;":"=f"(r):"f"(x)); return r; }

#define L2E 1.44269504088896f
#define LN2 0.69314718055995f

__global__ void __launch_bounds__(NTHR, 3)     // <=85 regs, 24 warps/SM
fdl_kernel(const float* __restrict__ logits,
           const int*   __restrict__ target,
           const float* __restrict__ cw,
           const float* __restrict__ fa,
           float*       __restrict__ out,
           int P2)
{
    __shared__ float s_cw[NCLS], s_fa[NCLS];
    __shared__ float s_red[64];
    __shared__ float s_fin[4][64];
    __shared__ bool  s_last;

    const int tid = threadIdx.x;
    if (tid < NCLS) { s_cw[tid] = cw[tid]; s_fa[tid] = fa[tid]; }
    if (tid < 64)   s_red[tid] = 0.f;
    __syncthreads();

    const int lane = tid & 31;
    const int pp   = lane & 15;          // pixel-pair slot within warp
    const int h    = lane >> 4;          // 0: classes 0..9, 1: classes 10..18(+dummy)
    const unsigned full = 0xffffffffu;

    // Per-thread accumulators for the 10 owned class slots.
    // Slot k -> class (h ? 10+k : k); h=1 slot 9 is a dummy (class "19", never hit).
    float ps[10], inter[10];
    unsigned cntp[3];                    // 10 u8 counters (max ~40 per slot)
#pragma unroll
    for (int k = 0; k < 10; ++k) { ps[k] = 0.f; inter[k] = 0.f; }
    cntp[0] = cntp[1] = cntp[2] = 0u;
    float aw = 0.f, anll = 0.f, afoc = 0.f;   // both halves accumulate -> exactly 2x

    const int warpGlobal = (blockIdx.x * (NTHR / 32)) + (tid >> 5);
    const int strideP    = NBLK * (NTHR / 32) * 16;       // pixel-pairs per sweep

    for (int ppgb = warpGlobal * 16; ppgb < P2; ppgb += strideP) {
        const int ppg = ppgb + pp;                        // this lane's pixel-pair
        const int b   = ppg >> 17;                        // / HW2
        const int hw2 = ppg & (HW2 - 1);
        const float2* base = (const float2*)(logits + (size_t)b * CHW) + hw2;

        // Load own 10 class streams (upper half: slot 9 duplicates class 18; zeroed)
        float2 e[10];
        float  Sx = 0.f, Sy = 0.f;
#pragma unroll
        for (int k = 0; k < 10; ++k) {
            const int cc = h ? ((k < 9) ? 10 + k : 18) : k;
            const float2 v = __ldg(base + (size_t)cc * HW2);
            float ex = ex2f(v.x * L2E);
            float ey = ex2f(v.y * L2E);
            if (k == 9) { ex = h ? 0.f : ex; ey = h ? 0.f : ey; }
            e[k].x = ex; e[k].y = ey;
            Sx += ex; Sy += ey;
        }
        // Full softmax denominators via cross-half exchange
        Sx += __shfl_xor_sync(full, Sx, 16);
        Sy += __shfl_xor_sync(full, Sy, 16);

        // Target pair (both halves read the same line; L1 broadcast)
        const int2 t2 = __ldg((const int2*)target + ppg);

        // Gather e_t from own classes, then combine across halves
        float etx = 0.f, ety = 0.f;
#pragma unroll
        for (int k = 0; k < 10; ++k) {
            const int cc = (h ? 10 : 0) + k;              // h=1,k=9 -> 19: never matches
            etx = (t2.x == cc) ? e[k].x : etx;
            ety = (t2.y == cc) ? e[k].y : ety;
        }
        etx += __shfl_xor_sync(full, etx, 16);
        ety += __shfl_xor_sync(full, ety, 16);

        const float invSx = rcpf(Sx);
        const float invSy = rcpf(Sy);

#pragma unroll
        for (int k = 0; k < 10; ++k)
            ps[k] = fmaf(e[k].x, invSx, fmaf(e[k].y, invSy, ps[k]));

#define PROC(TT, ET, INVS)                                                    \
        do {                                                                  \
            const float pt     = (ET) * (INVS);                               \
            const float log_pt = lg2f(pt) * LN2;                              \
            const float wt = s_cw[TT];                                        \
            const float at = s_fa[TT];                                        \
            aw  += wt;                                                        \
            anll = fmaf(wt, log_pt, anll);                                    \
            const float ptf = fmaxf(pt, 1e-8f);                               \
            const float om  = 1.f - ptf;                                      \
            afoc = fmaf(at * om * om, log_pt, afoc);                          \
            _Pragma("unroll")                                                 \
            for (int k = 0; k < 10; ++k) {                                    \
                const bool p = ((TT) == (h ? 10 : 0) + k);                    \
                inter[k] += p ? pt : 0.f;                                     \
                cntp[k >> 2] += p ? (1u << ((k & 3) * 8)) : 0u;               \
            }                                                                 \
        } while (0)

        PROC(t2.x, etx, invSx);
        PROC(t2.y, ety, invSy);
#undef PROC
    }

    // ---- Reduction. Per-class values: reduce within each 16-lane half. ----
#pragma unroll
    for (int k = 0; k < 10; ++k) {
        float v0 = ps[k], v1 = inter[k];
        float v2 = (float)((cntp[k >> 2] >> ((k & 3) * 8)) & 0xffu);
#pragma unroll
        for (int o = 8; o > 0; o >>= 1) {
            v0 += __shfl_down_sync(full, v0, o, 16);
            v1 += __shfl_down_sync(full, v1, o, 16);
            v2 += __shfl_down_sync(full, v2, o, 16);
        }
        const int cc = (h ? 10 : 0) + k;
        if (pp == 0 && cc < NCLS) {
            atomicAdd(&s_red[cc], v0);
            atomicAdd(&s_red[NCLS + cc], v1);
            atomicAdd(&s_red[2 * NCLS + cc], v2);
        }
    }
    {   // Scalars: full-warp reduce (values are 2x the true sums)
        float v0 = aw, v1 = anll, v2 = afoc;
#pragma unroll
        for (int o = 16; o > 0; o >>= 1) {
            v0 += __shfl_down_sync(full, v0, o);
            v1 += __shfl_down_sync(full, v1, o);
            v2 += __shfl_down_sync(full, v2, o);
        }
        if (lane == 0) {
            atomicAdd(&s_red[57], v0);
            atomicAdd(&s_red[58], v1);
            atomicAdd(&s_red[59], v2);
        }
    }
    __syncthreads();

    if (tid < 64) g_part[blockIdx.x][tid] = s_red[tid];

    // ---- Last block performs the final reduction (deterministic order) ----
    __threadfence();
    if (tid == 0) s_last = (atomicAdd(&g_sem, 1u) == NBLK - 1);
    __syncthreads();
    if (!s_last) return;

    if (tid == 0) g_sem = 0;    // reset for next graph replay
    __threadfence();

    {
        const int v = tid & 63;
        const int slice = tid >> 6;          // 0..3
        float acc = 0.f;
        for (int bb = slice; bb < NBLK; bb += 4) acc += g_part[bb][v];
        s_fin[slice][v] = acc;
    }
    __syncthreads();
    if (tid < 64)
        s_fin[0][tid] = s_fin[0][tid] + s_fin[1][tid] + s_fin[2][tid] + s_fin[3][tid];
    __syncthreads();

    if (tid == 0) {
        const float Pf    = (float)P2 * 2.0f;
        const float ce    = -s_fin[0][58] / s_fin[0][57];          // 2x cancels
        const float focal = -0.5f * s_fin[0][59] / Pf;             // undo 2x

        float sw = 0.f;
#pragma unroll
        for (int c = 0; c < NCLS; ++c) sw += s_cw[c];
        sw = fmaxf(sw, 1e-8f);

        float dsum = 0.f;
#pragma unroll
        for (int c = 0; c < NCLS; ++c) {
            const float dice = (2.f * s_fin[0][NCLS + c] + 1.f)
                             / (s_fin[0][c] + s_fin[0][2 * NCLS + c] + 1.f);
            dsum += dice * (s_cw[c] / sw);
        }
        const float dice_loss = 1.f - dsum;
        out[0] = 0.4f * ce + 0.3f * focal + 0.3f * dice_loss;
    }
}

extern "C" void kernel_launch(void* const* d_in, const int* in_sizes, int n_in,
                              void* d_out, int out_size)
{
    const float* logits = (const float*)d_in[0];
    const int*   target = (const int*)d_in[1];
    const float* cw     = (const float*)d_in[2];
    const float* fa     = (const float*)d_in[3];
    float*       out    = (float*)d_out;

    const int P2 = in_sizes[1] / 2;   // (B*H*W)/2 = 1,048,576 pixel-pairs

    fdl_kernel<<<NBLK, NTHR>>>(logits, target, cw, fa, out, P2);
}

// round 8
// speedup vs baseline: 1.0036x; 1.0036x over previous
#include <cuda_runtime.h>
#include <cstdint>

// Fixed-shape problem: logits [8,19,512,512] f32, target [8,512,512] (int32 on device)
#define NCLS   19
#define HW     262144          // 512*512
#define CHW    (NCLS * HW)
#define TILE   128             // pixels per tile (1 per thread)
#define NTHR   128
#define NBLK   592             // 4 CTAs per SM
#define STAGES 4
#define TXBYTES (NCLS * TILE * 4 + TILE * 4)   // 9728 + 512 = 10240

// Per-block partials: [0..18]=prob_sums, [19..37]=intersection, [38..56]=counts,
// [57]=sum w_t*log_pt, [58]=sum alpha*(1-pt)^2*log_pt
__device__ float    g_part[NBLK][64];
__device__ unsigned g_sem;      // zero-initialized; self-resetting

__device__ __forceinline__ float ex2f(float x){ float r; asm("ex2.approx.ftz.f32 %0,%1;":"=f"(r):"f"(x)); return r; }
__device__ __forceinline__ float lg2f(float x){ float r; asm("lg2.approx.ftz.f32 %0,%1;":"=f"(r):"f"(x)); return r; }
__device__ __forceinline__ float rcpf(float x){ float r; asm("rcp.approx.ftz.f32 %0,%1;":"=f"(r):"f"(x)); return r; }

__device__ __forceinline__ uint32_t smem_u32(const void* p) {
    return (uint32_t)__cvta_generic_to_shared(p);
}
__device__ __forceinline__ void mbar_init(uint32_t a, uint32_t cnt) {
    asm volatile("mbarrier.init.shared::cta.b64 [%0], %1;" :: "r"(a), "r"(cnt) : "memory");
}
__device__ __forceinline__ void mbar_expect_tx(uint32_t a, uint32_t bytes) {
    asm volatile("mbarrier.arrive.expect_tx.shared::cta.b64 _, [%0], %1;" :: "r"(a), "r"(bytes) : "memory");
}
__device__ __forceinline__ void mbar_wait(uint32_t a, int phase) {
    asm volatile(
        "{\n\t.reg .pred P;\n"
        "W_%=:\n\t"
        "mbarrier.try_wait.parity.acquire.cta.shared::cta.b64 P, [%0], %1;\n\t"
        "@!P bra W_%=;\n\t}"
        :: "r"(a), "r"(phase) : "memory");
}
__device__ __forceinline__ void bulk_g2s(uint32_t dst, const void* src, uint32_t bytes, uint32_t mbar) {
    asm volatile(
        "cp.async.bulk.shared::cluster.global.mbarrier::complete_tx::bytes [%0], [%1], %2, [%3];"
        :: "r"(dst), "l"(src), "r"(bytes), "r"(mbar) : "memory");
}

#define L2E 1.44269504088896f
#define LN2 0.69314718055995f

__global__ void __launch_bounds__(NTHR, 4)
fdl_kernel(const float* __restrict__ logits,
           const int*   __restrict__ target,
           const float* __restrict__ cw,
           const float* __restrict__ fa,
           float*       __restrict__ out,
           int P)
{
    __shared__ float sb[STAGES][NCLS][TILE];     // 38912 B
    __shared__ int   st[STAGES][TILE];           //  2048 B
    __shared__ unsigned long long mbar[STAGES];
    __shared__ float s_cw[NCLS], s_fa[NCLS];
    __shared__ float s_red[64];
    __shared__ float s_fin[2][64];
    __shared__ bool  s_last;

    const int tid = threadIdx.x;
    const int NTILES = P / TILE;                 // 16384

    if (tid < NCLS) { s_cw[tid] = cw[tid]; s_fa[tid] = fa[tid]; }
    if (tid < 64)   s_red[tid] = 0.f;
    if (tid == 0) {
#pragma unroll
        for (int s = 0; s < STAGES; ++s) mbar_init(smem_u32(&mbar[s]), 1);
        asm volatile("fence.proxy.async.shared::cta;" ::: "memory");
    }
    __syncthreads();

    // ---- TMA issue helper (tid 0 only): tile t -> stage s ----
#define ISSUE(T, S)                                                            \
    do {                                                                       \
        const uint32_t mb = smem_u32(&mbar[S]);                                \
        mbar_expect_tx(mb, TXBYTES);                                           \
        const int      bb    = (T) >> 11;                 /* tile/2048 */      \
        const uint32_t hwoff = ((uint32_t)(T) << 7) & (HW - 1);                \
        const float* src0 = logits + (size_t)bb * CHW + hwoff;                 \
        _Pragma("unroll")                                                      \
        for (int c = 0; c < NCLS; ++c)                                         \
            bulk_g2s(smem_u32(&sb[S][c][0]), src0 + (size_t)c * HW,            \
                     TILE * 4, mb);                                            \
        bulk_g2s(smem_u32(&st[S][0]), target + (size_t)(T) * TILE,             \
                 TILE * 4, mb);                                                \
    } while (0)

    if (tid == 0) {
#pragma unroll
        for (int s = 0; s < STAGES; ++s) {
            const int t0 = blockIdx.x + s * NBLK;
            if (t0 < NTILES) ISSUE(t0, s);
        }
    }

    // Per-thread accumulators
    float ps[NCLS], iq[NCLS];        // iq = 512*count + sum(pt)
#pragma unroll
    for (int c = 0; c < NCLS; ++c) { ps[c] = 0.f; iq[c] = 0.f; }
    float anll = 0.f, afoc = 0.f;

    int k = 0;
    for (int t = blockIdx.x; t < NTILES; t += NBLK, ++k) {
        const int s  = k & (STAGES - 1);
        const int ph = (k >> 2) & 1;
        mbar_wait(smem_u32(&mbar[s]), ph);

        const int tt = st[s][tid];

        float e[NCLS];
        float S = 0.f;
#pragma unroll
        for (int c = 0; c < NCLS; ++c) {
            const float v = sb[s][c][tid];
            e[c] = ex2f(v * L2E);
            S += e[c];
        }
        float et = e[0];
#pragma unroll
        for (int c = 1; c < NCLS; ++c) et = (tt == c) ? e[c] : et;

        const float invS   = rcpf(S);
        const float pt     = et * invS;
        const float log_pt = lg2f(pt) * LN2;

        anll = fmaf(s_cw[tt], log_pt, anll);
        const float ptf = fmaxf(pt, 1e-8f);
        const float om  = 1.f - ptf;
        afoc = fmaf(s_fa[tt] * om * om, log_pt, afoc);

        const float qadd = pt + 512.f;
#pragma unroll
        for (int c = 0; c < NCLS; ++c) {
            ps[c] = fmaf(e[c], invS, ps[c]);
            iq[c] += (tt == c) ? qadd : 0.f;
        }

        __syncthreads();          // all lanes done reading stage s
        if (tid == 0) {
            const int nt = t + STAGES * NBLK;
            if (nt < NTILES) ISSUE(nt, s);
        }
    }
#undef ISSUE

    // ---- Block reduction: unpack iq, warp shuffles, smem atomics ----
    const unsigned full = 0xffffffffu;
    const bool lead = ((tid & 31) == 0);
#pragma unroll
    for (int c = 0; c < NCLS; ++c) {
        const float q  = iq[c];
        const float cf = floorf(q * (1.f / 512.f));   // exact: events <= 28
        float v0 = ps[c], v1 = q - 512.f * cf, v2 = cf;
#pragma unroll
        for (int o = 16; o > 0; o >>= 1) {
            v0 += __shfl_down_sync(full, v0, o);
            v1 += __shfl_down_sync(full, v1, o);
            v2 += __shfl_down_sync(full, v2, o);
        }
        if (lead) {
            atomicAdd(&s_red[c], v0);
            atomicAdd(&s_red[NCLS + c], v1);
            atomicAdd(&s_red[2 * NCLS + c], v2);
        }
    }
    {
        float v0 = anll, v1 = afoc;
#pragma unroll
        for (int o = 16; o > 0; o >>= 1) {
            v0 += __shfl_down_sync(full, v0, o);
            v1 += __shfl_down_sync(full, v1, o);
        }
        if (lead) {
            atomicAdd(&s_red[57], v0);
            atomicAdd(&s_red[58], v1);
        }
    }
    __syncthreads();

    if (tid < 64) g_part[blockIdx.x][tid] = s_red[tid];

    // ---- Last block performs the final reduction (deterministic order) ----
    __threadfence();
    if (tid == 0) s_last = (atomicAdd(&g_sem, 1u) == NBLK - 1);
    __syncthreads();
    if (!s_last) return;

    if (tid == 0) g_sem = 0;     // reset for next graph replay
    __threadfence();

    {
        const int v = tid & 63;
        const int slice = tid >> 6;           // 0..1
        float acc = 0.f;
        for (int bb = slice; bb < NBLK; bb += 2) acc += g_part[bb][v];
        s_fin[slice][v] = acc;
    }
    __syncthreads();
    if (tid < 64) s_fin[0][tid] = s_fin[0][tid] + s_fin[1][tid];
    __syncthreads();

    if (tid == 0) {
        // sum w_t derived from per-class counts
        float swt = 0.f;
#pragma unroll
        for (int c = 0; c < NCLS; ++c) swt = fmaf(s_fin[0][2 * NCLS + c], s_cw[c], swt);

        const float ce    = -s_fin[0][57] / swt;
        const float focal = -s_fin[0][58] / (float)P;

        float sw = 0.f;
#pragma unroll
        for (int c = 0; c < NCLS; ++c) sw += s_cw[c];
        sw = fmaxf(sw, 1e-8f);

        float dsum = 0.f;
#pragma unroll
        for (int c = 0; c < NCLS; ++c) {
            const float dice = (2.f * s_fin[0][NCLS + c] + 1.f)
                             / (s_fin[0][c] + s_fin[0][2 * NCLS + c] + 1.f);
            dsum += dice * (s_cw[c] / sw);
        }
        const float dice_loss = 1.f - dsum;
        out[0] = 0.4f * ce + 0.3f * focal + 0.3f * dice_loss;
    }
}

extern "C" void kernel_launch(void* const* d_in, const int* in_sizes, int n_in,
                              void* d_out, int out_size)
{
    const float* logits = (const float*)d_in[0];
    const int*   target = (const int*)d_in[1];
    const float* cw     = (const float*)d_in[2];
    const float* fa     = (const float*)d_in[3];
    float*       out    = (float*)d_out;

    const int P = in_sizes[1];    // B*H*W = 2,097,152

    fdl_kernel<<<NBLK, NTHR>>>(logits, target, cw, fa, out, P);
}

// round 9
// speedup vs baseline: 1.1832x; 1.1790x over previous
#include <cuda_runtime.h>

// Fixed-shape problem: logits [8,19,512,512] f32, target [8,512,512] (int32 on device)
#define NCLS 19
#define HW   262144           // 512*512
#define CHW  (NCLS * HW)
#define NBLK 296              // 2 CTAs per SM, exactly resident
#define NTHR 256

// Per-block partials: [0..18]=prob_sums, [19..37]=intersection, [38..56]=counts,
// [57]=sum w_t*log_pt, [58]=sum alpha*(1-pt)^2*log_pt
__device__ float    g_part[NBLK][64];
__device__ unsigned g_sem;     // zero-initialized; self-resetting

__device__ __forceinline__ float ex2f(float x){ float r; asm("ex2.approx.ftz.f32 %0,%1;":"=f"(r):"f"(x)); return r; }
__device__ __forceinline__ float lg2f(float x){ float r; asm("lg2.approx.ftz.f32 %0,%1;":"=f"(r):"f"(x)); return r; }
__device__ __forceinline__ float rcpf(float x){ float r; asm("rcp.approx.ftz.f32 %0,%1;":"=f"(r):"f"(x)); return r; }

#define L2E 1.44269504088896f
#define LN2 0.69314718055995f

__global__ void __launch_bounds__(NTHR, 2)      // <=128 regs; ~110 live -> no spill
fdl_kernel(const float* __restrict__ logits,
           const int*   __restrict__ target,
           const float* __restrict__ cw,
           const float* __restrict__ fa,
           float*       __restrict__ out,
           int P)
{
    __shared__ float s_cw[NCLS], s_fa[NCLS];
    __shared__ float s_red[64];
    __shared__ float s_fin[4][64];
    __shared__ bool  s_last;

    const int tid = threadIdx.x;
    if (tid < NCLS) { s_cw[tid] = cw[tid]; s_fa[tid] = fa[tid]; }
    if (tid < 64)   s_red[tid] = 0.f;
    __syncthreads();

    // Per-thread accumulators
    float ps[NCLS], iq[NCLS];        // iq = 512*count + sum(pt); exact (<=28 events)
#pragma unroll
    for (int c = 0; c < NCLS; ++c) { ps[c] = 0.f; iq[c] = 0.f; }
    float anll = 0.f, afoc = 0.f;

    const int stride = NBLK * NTHR;  // 75776

    // ---- Software-pipelined mainloop: loads for iter k+1 issue during compute k
    int pix = blockIdx.x * NTHR + tid;          // always < P on entry
    float l[NCLS];
    {
        const int b  = pix >> 18;
        const int hw = pix & (HW - 1);
        const float* base = logits + (size_t)b * CHW + hw;
#pragma unroll
        for (int c = 0; c < NCLS; ++c) l[c] = __ldcs(base + (size_t)c * HW);
    }
    int tt = __ldg(target + pix);

    for (;;) {
        const int next = pix + stride;

        // Consume l[] immediately: e = 2^(l*log2e). This frees l for the prefetch.
        float e[NCLS];
#pragma unroll
        for (int c = 0; c < NCLS; ++c) e[c] = ex2f(l[c] * L2E);

        // Prefetch next iteration (overlaps with the remaining compute below)
        int tt_next = 0;
        const bool more = (next < P);            // warp-uniform (P, starts 32-aligned)
        if (more) {
            const int b  = next >> 18;
            const int hw = next & (HW - 1);
            const float* base = logits + (size_t)b * CHW + hw;
#pragma unroll
            for (int c = 0; c < NCLS; ++c) l[c] = __ldcs(base + (size_t)c * HW);
            tt_next = __ldg(target + next);
        }

        // Remaining compute on e[] / tt
        float S = 0.f;
#pragma unroll
        for (int c = 0; c < NCLS; ++c) S += e[c];
        float et = e[0];
#pragma unroll
        for (int c = 1; c < NCLS; ++c) et = (tt == c) ? e[c] : et;

        const float invS   = rcpf(S);
        const float pt     = et * invS;
        const float log_pt = lg2f(pt) * LN2;

        anll = fmaf(s_cw[tt], log_pt, anll);
        const float ptf = fmaxf(pt, 1e-8f);
        const float om  = 1.f - ptf;
        afoc = fmaf(s_fa[tt] * om * om, log_pt, afoc);

        const float qadd = pt + 512.f;
#pragma unroll
        for (int c = 0; c < NCLS; ++c) {
            ps[c] = fmaf(e[c], invS, ps[c]);
            iq[c] += (tt == c) ? qadd : 0.f;
        }

        if (!more) break;
        pix = next;
        tt  = tt_next;
    }

    // ---- Block reduction: unpack iq, warp shuffles, smem atomics ----
    const unsigned full = 0xffffffffu;
    const bool lead = ((tid & 31) == 0);
#pragma unroll
    for (int c = 0; c < NCLS; ++c) {
        const float q  = iq[c];
        const float cf = floorf(q * (1.f / 512.f));   // exact count
        float v0 = ps[c], v1 = q - 512.f * cf, v2 = cf;
#pragma unroll
        for (int o = 16; o > 0; o >>= 1) {
            v0 += __shfl_down_sync(full, v0, o);
            v1 += __shfl_down_sync(full, v1, o);
            v2 += __shfl_down_sync(full, v2, o);
        }
        if (lead) {
            atomicAdd(&s_red[c], v0);
            atomicAdd(&s_red[NCLS + c], v1);
            atomicAdd(&s_red[2 * NCLS + c], v2);
        }
    }
    {
        float v0 = anll, v1 = afoc;
#pragma unroll
        for (int o = 16; o > 0; o >>= 1) {
            v0 += __shfl_down_sync(full, v0, o);
            v1 += __shfl_down_sync(full, v1, o);
        }
        if (lead) {
            atomicAdd(&s_red[57], v0);
            atomicAdd(&s_red[58], v1);
        }
    }
    __syncthreads();

    if (tid < 64) g_part[blockIdx.x][tid] = s_red[tid];

    // ---- Last block performs the final reduction (deterministic order) ----
    __threadfence();
    if (tid == 0) s_last = (atomicAdd(&g_sem, 1u) == NBLK - 1);
    __syncthreads();
    if (!s_last) return;

    if (tid == 0) g_sem = 0;    // reset for next graph replay
    __threadfence();

    {
        const int v = tid & 63;
        const int slice = tid >> 6;          // 0..3
        float acc = 0.f;
        for (int bb = slice; bb < NBLK; bb += 4) acc += g_part[bb][v];
        s_fin[slice][v] = acc;
    }
    __syncthreads();
    if (tid < 64)
        s_fin[0][tid] = s_fin[0][tid] + s_fin[1][tid] + s_fin[2][tid] + s_fin[3][tid];
    __syncthreads();

    if (tid == 0) {
        float swt = 0.f;                      // sum w_t from per-class counts
#pragma unroll
        for (int c = 0; c < NCLS; ++c) swt = fmaf(s_fin[0][2 * NCLS + c], s_cw[c], swt);

        const float ce    = -s_fin[0][57] / swt;
        const float focal = -s_fin[0][58] / (float)P;

        float sw = 0.f;
#pragma unroll
        for (int c = 0; c < NCLS; ++c) sw += s_cw[c];
        sw = fmaxf(sw, 1e-8f);

        float dsum = 0.f;
#pragma unroll
        for (int c = 0; c < NCLS; ++c) {
            const float dice = (2.f * s_fin[0][NCLS + c] + 1.f)
                             / (s_fin[0][c] + s_fin[0][2 * NCLS + c] + 1.f);
            dsum += dice * (s_cw[c] / sw);
        }
        const float dice_loss = 1.f - dsum;
        out[0] = 0.4f * ce + 0.3f * focal + 0.3f * dice_loss;
    }
}

extern "C" void kernel_launch(void* const* d_in, const int* in_sizes, int n_in,
                              void* d_out, int out_size)
{
    const float* logits = (const float*)d_in[0];
    const int*   target = (const int*)d_in[1];
    const float* cw     = (const float*)d_in[2];
    const float* fa     = (const float*)d_in[3];
    float*       out    = (float*)d_out;

    const int P = in_sizes[1];   // B*H*W = 2,097,152

    fdl_kernel<<<NBLK, NTHR>>>(logits, target, cw, fa, out, P);
}